// round 3
// baseline (speedup 1.0000x reference)
#include <cuda_runtime.h>
#include <math.h>

#define B_ 8
#define S_ 2048
#define DSTATE 1024
#define H_ 16
#define DH_ 64
#define PROJW 4096

// Scratch (device globals: allocation-free, graph-capturable)
__device__ float g_proj[(size_t)B_ * S_ * PROJW];   // 256 MB
__device__ float g_hseq[(size_t)B_ * S_ * DSTATE];  // 64 MB
__device__ float g_y[(size_t)B_ * S_ * DSTATE];     // 64 MB

// Device-side buffer selector: 0 = external pointer, 1..3 = scratch globals.
__device__ __forceinline__ float* sel_buf(int s, const void* ext) {
    switch (s) {
        case 1: return g_proj;
        case 2: return g_hseq;
        case 3: return g_y;
        default: return (float*)ext;
    }
}

// ---------------------------------------------------------------------------
// GEMM: C[M,N] = A[M,K] @ B[K,N], row-major, all dims multiples of 128/8.
// 128x128 block tile, BK=8, 8x8 per-thread microtile, 256 threads.
// Static smem: 8 KB. Well under the 48 KB default limit.
// ---------------------------------------------------------------------------
__global__ __launch_bounds__(256) void gemm128(const void* Aext, int a_sel,
                                               const float* __restrict__ Bm,
                                               void* Cext, int c_sel,
                                               int M, int N, int K)
{
    const float* __restrict__ A = sel_buf(a_sel, Aext);
    float* __restrict__ C = sel_buf(c_sel, Cext);

    __shared__ float As[8][128];
    __shared__ float Bs[8][128];

    const int tid = threadIdx.x;
    const int bm = blockIdx.y * 128;
    const int bn = blockIdx.x * 128;
    const int tx = tid & 15;
    const int ty = tid >> 4;

    float acc[8][8] = {};

    const int am = tid >> 1;
    const int ak = (tid & 1) * 4;
    const int bk  = tid >> 5;
    const int bn4 = (tid & 31) * 4;

    const float* Aptr = A + (size_t)(bm + am) * K + ak;
    const float* Bptr = Bm + (size_t)bk * N + bn + bn4;

    for (int k0 = 0; k0 < K; k0 += 8) {
        float4 av = *(const float4*)(Aptr + k0);
        float4 bv = *(const float4*)(Bptr + (size_t)k0 * N);
        As[ak + 0][am] = av.x;
        As[ak + 1][am] = av.y;
        As[ak + 2][am] = av.z;
        As[ak + 3][am] = av.w;
        *(float4*)&Bs[bk][bn4] = bv;
        __syncthreads();

#pragma unroll
        for (int k = 0; k < 8; k++) {
            float a[8], b[8];
            *(float4*)&a[0] = *(const float4*)&As[k][ty * 8];
            *(float4*)&a[4] = *(const float4*)&As[k][ty * 8 + 4];
            *(float4*)&b[0] = *(const float4*)&Bs[k][tx * 8];
            *(float4*)&b[4] = *(const float4*)&Bs[k][tx * 8 + 4];
#pragma unroll
            for (int i = 0; i < 8; i++)
#pragma unroll
                for (int j = 0; j < 8; j++)
                    acc[i][j] = fmaf(a[i], b[j], acc[i][j]);
        }
        __syncthreads();
    }

#pragma unroll
    for (int i = 0; i < 8; i++) {
        float* Crow = C + (size_t)(bm + ty * 8 + i) * N + bn + tx * 8;
        *(float4*)Crow       = make_float4(acc[i][0], acc[i][1], acc[i][2], acc[i][3]);
        *(float4*)(Crow + 4) = make_float4(acc[i][4], acc[i][5], acc[i][6], acc[i][7]);
    }
}

// ---------------------------------------------------------------------------
// Recurrence: one block per (b, h). 64 threads. Each thread e holds column e
// of the three 64x64 weight matrices in REGISTERS (192 regs). Only 512 B of
// static smem (h state + r*h buffer) -> no smem-limit issue, no crossbar
// traffic for weights.
//   out[e] = sum_d h[d] * W[h][d][e]   (thread e owns output column e)
// ---------------------------------------------------------------------------
__global__ __launch_bounds__(64, 1) void recur_kernel(const float* __restrict__ Wall)
{
    __shared__ float hs[64];
    __shared__ float rh[64];

    const int b = blockIdx.x >> 4;
    const int h = blockIdx.x & 15;
    const int e = threadIdx.x;

    // Register-resident weight columns: wc/wf/wr[d] = W[h][d][e]
    float wc[64], wf[64], wr[64];
    const float* Wc = Wall + (size_t)h * 4096 + e;
    const float* Wf = Wall + (size_t)(16 + h) * 4096 + e;
    const float* Wr = Wall + (size_t)(32 + h) * 4096 + e;
#pragma unroll
    for (int d = 0; d < 64; d++) {
        wc[d] = Wc[d * 64];
        wf[d] = Wf[d * 64];
        wr[d] = Wr[d * 64];
    }

    hs[e] = 0.f;
    __syncthreads();

    const float* xp = g_proj + (size_t)b * S_ * PROJW + h * DH_ + e;
    float* op = g_hseq + (size_t)b * S_ * DSTATE + h * DH_ + e;

    float xi = xp[0], xf = xp[1024], xr = xp[2048];

    for (int t = 0; t < S_; t++) {
        xp += PROJW;
        float nxi = 0.f, nxf = 0.f, nxr = 0.f;
        if (t + 1 < S_) { nxi = xp[0]; nxf = xp[1024]; nxr = xp[2048]; }

        const float hself = hs[e];
        float ar = 0.f, af = 0.f;
#pragma unroll
        for (int d4 = 0; d4 < 64; d4 += 4) {
            float4 hv = *(const float4*)&hs[d4];   // broadcast LDS.128
            ar = fmaf(hv.x, wr[d4 + 0], ar);
            af = fmaf(hv.x, wf[d4 + 0], af);
            ar = fmaf(hv.y, wr[d4 + 1], ar);
            af = fmaf(hv.y, wf[d4 + 1], af);
            ar = fmaf(hv.z, wr[d4 + 2], ar);
            af = fmaf(hv.z, wf[d4 + 2], af);
            ar = fmaf(hv.w, wr[d4 + 3], ar);
            af = fmaf(hv.w, wf[d4 + 3], af);
        }
        float r = 1.f / (1.f + __expf(-(xr + ar)));
        float f = 1.f / (1.f + __expf(-(xf + af)));
        rh[e] = r * hself;
        __syncthreads();   // rh visible; all hs reads of this step done

        float ac = 0.f;
#pragma unroll
        for (int d4 = 0; d4 < 64; d4 += 4) {
            float4 rv = *(const float4*)&rh[d4];   // broadcast LDS.128
            ac = fmaf(rv.x, wc[d4 + 0], ac);
            ac = fmaf(rv.y, wc[d4 + 1], ac);
            ac = fmaf(rv.z, wc[d4 + 2], ac);
            ac = fmaf(rv.w, wc[d4 + 3], ac);
        }
        float c = tanhf(xi + ac);
        float hnew = f * hself + (1.f - f) * c;

        hs[e] = hnew;      // safe: all hs reads happened before the sync above
        *op = hnew;
        op += DSTATE;
        xi = nxi; xf = nxf; xr = nxr;
        __syncthreads();   // hs update visible before next step
    }
}

// ---------------------------------------------------------------------------
// Gated SiLU + RMSNorm: one block per (b,s) row.
// ---------------------------------------------------------------------------
__global__ __launch_bounds__(256) void gate_norm_kernel(const float* __restrict__ nw)
{
    const int row = blockIdx.x;
    const float* g    = g_proj + (size_t)row * PROJW + 3072;
    const float* hrow = g_hseq + (size_t)row * DSTATE;
    float* yrow = g_y + (size_t)row * DSTATE;
    const int tid = threadIdx.x;

    float v[4];
    float ss = 0.f;
#pragma unroll
    for (int i = 0; i < 4; i++) {
        int c = tid + i * 256;
        float gv = g[c];
        float hv = hrow[c];
        float yv = hv * gv / (1.f + __expf(-gv));
        v[i] = yv;
        ss += yv * yv;
    }

    __shared__ float red[8];
#pragma unroll
    for (int o = 16; o; o >>= 1) ss += __shfl_xor_sync(0xffffffffu, ss, o);
    if ((tid & 31) == 0) red[tid >> 5] = ss;
    __syncthreads();
    if (tid < 8) {
        float s = red[tid];
#pragma unroll
        for (int o = 4; o; o >>= 1) s += __shfl_xor_sync(0xffu, s, o);
        if (tid == 0) red[0] = s;
    }
    __syncthreads();
    const float scale = rsqrtf(red[0] * (1.f / 1024.f) + 1e-6f);

#pragma unroll
    for (int i = 0; i < 4; i++) {
        int c = tid + i * 256;
        yrow[c] = v[i] * scale * nw[c];
    }
}

// ---------------------------------------------------------------------------
// Launch — kernel launches ONLY (graph-capturable).
// ---------------------------------------------------------------------------
extern "C" void kernel_launch(void* const* d_in, const int* in_sizes, int n_in,
                              void* d_out, int out_size)
{
    const float* x      = (const float*)d_in[0];  // [8,2048,1024]
    const float* w_in   = (const float*)d_in[1];  // [1024,4096]
    const float* s_w    = (const float*)d_in[2];  // [48,64,64]
    const float* norm_w = (const float*)d_in[3];  // [1024]
    const float* w_out  = (const float*)d_in[4];  // [1024,1024]

    const int M = B_ * S_;  // 16384

    // 1) input projection: x[16384,1024] @ w_in[1024,4096] -> g_proj
    {
        dim3 grid(PROJW / 128, M / 128);
        gemm128<<<grid, 256>>>(x, /*a_sel=*/0, w_in, nullptr, /*c_sel=*/1,
                               M, PROJW, 1024);
    }

    // 2) recurrence over time -> g_hseq
    recur_kernel<<<B_ * H_, 64>>>(s_w);

    // 3) gated silu + rmsnorm -> g_y
    gate_norm_kernel<<<M, 256>>>(norm_w);

    // 4) output projection: g_y[16384,1024] @ w_out[1024,1024] -> d_out
    {
        dim3 grid(1024 / 128, M / 128);
        gemm128<<<grid, 256>>>(nullptr, /*a_sel=*/3, w_out, d_out, /*c_sel=*/0,
                               M, 1024, 1024);
    }
}